// round 1
// baseline (speedup 1.0000x reference)
#include <cuda_runtime.h>
#include <cuda_bf16.h>

// Problem constants
#define CC      64      // channels
#define DI      128     // d_inner
#define DS      16      // d_state
#define LL      4096    // sequence length H*W
#define BB      4       // batch
#define NTOK    (BB*LL) // 16384 tokens
#define NCHUNK  64
#define CSIZE   64      // LL / NCHUNK

// ---------------- scratch (device globals; no allocation allowed) ------------
__device__ float g_hn   [NTOK*CC];        // LayerNorm output [m, c]
__device__ float g_seqT [BB*CC*LL];       // pre-LN activations, transposed [b,c,l]
__device__ float g_xm   [NTOK*DI];        // in_proj first half [m, d]
__device__ float g_z    [NTOK*DI];        // in_proj second half [m, d]
__device__ float g_xc   [NTOK*DI];        // conv1d+silu output [m, d]
__device__ float g_dt   [NTOK*DI];        // softplus(dt) [m, d]
__device__ float g_Bm   [NTOK*DS];        // [m, s]
__device__ float g_Cm   [NTOK*DS];        // [m, s]
__device__ float g_ysT  [BB*DI*LL];       // scan output, transposed [b,d,l]
__device__ float g_hend [BB*NCHUNK*DI*DS];
__device__ float g_hinit[BB*NCHUNK*DI*DS];
__device__ float g_sumdt[BB*NCHUNK*DI];

// ============================================================================
// K1: axial depthwise convs + 1x1 conv + BN + ReLU + LayerNorm
// one block per (b, h) image row; 64 tokens x 64 channels in smem
// ============================================================================
__global__ __launch_bounds__(256) void k1_front(
    const float* __restrict__ x,
    const float* __restrict__ dwh_w, const float* __restrict__ dwh_b,
    const float* __restrict__ dww_w, const float* __restrict__ dww_b,
    const float* __restrict__ conv_w, const float* __restrict__ conv_b,
    const float* __restrict__ bn_g, const float* __restrict__ bn_b,
    const float* __restrict__ bn_m, const float* __restrict__ bn_v,
    const float* __restrict__ ln_g, const float* __restrict__ ln_b)
{
    __shared__ float sm[64][65];       // m[c][w], later t[c][w]
    __shared__ float scw[64*64];       // 1x1 conv weights
    __shared__ float red_s[64][4];
    __shared__ float red_q[64][4];
    __shared__ float s_mu[64], s_rs[64];

    int bh = blockIdx.x;               // 0..255
    int b = bh >> 6, h = bh & 63;
    int tid = threadIdx.x;

    for (int i = tid; i < 4096; i += 256) scw[i] = conv_w[i];

    // m = x + axial dw convs + biases
    for (int i = tid; i < 4096; i += 256) {
        int c = i >> 6, w = i & 63;
        const float* xb = x + ((b*64 + c)*64)*64;   // + h*64 + w
        float center = xb[h*64 + w];
        float acc = center;
        float wh0 = dwh_w[c*3+0], wh1 = dwh_w[c*3+1], wh2 = dwh_w[c*3+2];
        if (h > 0)  acc += wh0 * xb[(h-1)*64 + w];
        acc += wh1 * center;
        if (h < 63) acc += wh2 * xb[(h+1)*64 + w];
        float ww0 = dww_w[c*3+0], ww1 = dww_w[c*3+1], ww2 = dww_w[c*3+2];
        if (w > 0)  acc += ww0 * xb[h*64 + w - 1];
        acc += ww1 * center;
        if (w < 63) acc += ww2 * xb[h*64 + w + 1];
        acc += dwh_b[c] + dww_b[c];
        sm[c][w] = acc;
    }
    __syncthreads();

    // 1x1 conv + BN + ReLU into registers
    float t[16];
    #pragma unroll
    for (int j = 0; j < 16; j++) {
        int i = tid + j*256;
        int o = i >> 6, w = i & 63;
        float acc = 0.f;
        #pragma unroll 8
        for (int c = 0; c < 64; c++) acc += scw[o*64+c]*sm[c][w];
        acc += conv_b[o];
        float rs = rsqrtf(bn_v[o] + 1e-5f);
        acc = (acc - bn_m[o]) * rs * bn_g[o] + bn_b[o];
        t[j] = fmaxf(acc, 0.f);
    }
    __syncthreads();
    #pragma unroll
    for (int j = 0; j < 16; j++) {
        int i = tid + j*256;
        sm[i>>6][i&63] = t[j];
    }
    __syncthreads();

    // LayerNorm over channels per token
    {
        int w = tid & 63, p = tid >> 6;
        float s = 0.f, q = 0.f;
        #pragma unroll
        for (int c = p*16; c < p*16+16; c++) { float v = sm[c][w]; s += v; q += v*v; }
        red_s[w][p] = s; red_q[w][p] = q;
    }
    __syncthreads();
    if (tid < 64) {
        float s = red_s[tid][0]+red_s[tid][1]+red_s[tid][2]+red_s[tid][3];
        float q = red_q[tid][0]+red_q[tid][1]+red_q[tid][2]+red_q[tid][3];
        float mu = s * (1.f/64.f);
        float var = q * (1.f/64.f) - mu*mu;
        s_mu[tid] = mu;
        s_rs[tid] = rsqrtf(var + 1e-5f);
    }
    __syncthreads();

    int mbase = b*LL + h*64;   // token base for this row
    // hn writes: c fastest -> coalesced
    for (int i = tid; i < 4096; i += 256) {
        int w = i >> 6, c = i & 63;
        float v = sm[c][w];
        g_hn[(mbase + w)*64 + c] = (v - s_mu[w]) * s_rs[w] * ln_g[c] + ln_b[c];
    }
    // seqT writes [b,c,l]: w fastest -> coalesced
    for (int i = tid; i < 4096; i += 256) {
        int c = i >> 6, w = i & 63;
        g_seqT[(b*64 + c)*LL + h*64 + w] = sm[c][w];
    }
}

// ============================================================================
// K2: in_proj GEMM  xz[m, 0..255] = hn[m, :] @ W^T ; split into xm / z
// block tile: 64 tokens x 64 outputs
// ============================================================================
__global__ __launch_bounds__(256) void k2_inproj(const float* __restrict__ W)
{
    __shared__ float sa[64][65];   // hn tile [token][k]
    __shared__ float sw[64][65];   // weight tile [o][k]
    int m0 = blockIdx.x * 64;
    int n0 = blockIdx.y * 64;
    int tid = threadIdx.x;
    for (int i = tid; i < 4096; i += 256) {
        int r = i >> 6, kk = i & 63;
        sa[r][kk] = g_hn[(m0+r)*64 + kk];
        sw[r][kk] = W[(n0+r)*64 + kk];
    }
    __syncthreads();

    int o  = tid & 63;     // output channel (lane-consecutive -> coalesced writes)
    int tb = tid >> 6;     // token base
    float acc[16];
    #pragma unroll
    for (int j = 0; j < 16; j++) acc[j] = 0.f;
    #pragma unroll 8
    for (int k = 0; k < 64; k++) {
        float wv = sw[o][k];
        #pragma unroll
        for (int j = 0; j < 16; j++) acc[j] += sa[tb + j*4][k] * wv;
    }
    int og = n0 + o;
    #pragma unroll
    for (int j = 0; j < 16; j++) {
        int m = m0 + tb + j*4;
        if (og < 128) g_xm[m*128 + og]       = acc[j];
        else          g_z [m*128 + og - 128] = acc[j];
    }
}

// ============================================================================
// K3: causal depthwise conv1d (k=4, left pad 3) + SiLU
// ============================================================================
__global__ __launch_bounds__(256) void k3_conv1d(
    const float* __restrict__ cw, const float* __restrict__ cb)
{
    int i = blockIdx.x*256 + threadIdx.x;      // over NTOK*DI
    int d = i & 127;
    int m = i >> 7;
    int l = m & (LL-1);
    float acc = cb[d];
    acc += cw[d*4+3] * g_xm[i];
    if (l >= 1) acc += cw[d*4+2] * g_xm[i - 128];
    if (l >= 2) acc += cw[d*4+1] * g_xm[i - 256];
    if (l >= 3) acc += cw[d*4+0] * g_xm[i - 384];
    float sg = 1.f/(1.f + __expf(-acc));
    g_xc[i] = acc * sg;
}

// ============================================================================
// K4: x_proj (36x128) + dt_proj (128x4) + softplus; writes dt, Bm, Cm
// block = 32 tokens
// ============================================================================
__global__ __launch_bounds__(256) void k4_xproj(
    const float* __restrict__ xpw,   // [36][128]
    const float* __restrict__ dtw,   // [128][4]
    const float* __restrict__ dtb)   // [128]
{
    __shared__ float sxc[32][129];
    __shared__ float sw[36][128];
    __shared__ float sdbc[32][37];
    int m0 = blockIdx.x * 32;
    int tid = threadIdx.x;
    for (int i = tid; i < 32*128; i += 256)
        sxc[i>>7][i&127] = g_xc[(m0 + (i>>7))*128 + (i&127)];
    for (int i = tid; i < 36*128; i += 256) sw[i>>7][i&127] = xpw[i];
    __syncthreads();

    for (int i = tid; i < 32*36; i += 256) {
        int t = i / 36, e = i % 36;
        float acc = 0.f;
        #pragma unroll 8
        for (int k = 0; k < 128; k++) acc += sxc[t][k]*sw[e][k];
        sdbc[t][e] = acc;
    }
    __syncthreads();

    for (int i = tid; i < 512; i += 256) {
        int t = i >> 4, s = i & 15;
        g_Bm[(m0+t)*16 + s] = sdbc[t][4 + s];
        g_Cm[(m0+t)*16 + s] = sdbc[t][20 + s];
    }
    for (int i = tid; i < 4096; i += 256) {
        int t = i >> 7, d = i & 127;
        float acc = dtb[d];
        #pragma unroll
        for (int r = 0; r < 4; r++) acc += sdbc[t][r]*dtw[d*4+r];
        g_dt[(m0+t)*128 + d] = (acc > 20.f) ? acc : log1pf(__expf(acc));
    }
}

// ============================================================================
// K5 (phase A): per-chunk local scan starting at 0 -> h_end, sum(dt)
// warp handles (b, chunk, 2 d's); lane = s + 16*(d&1)
// ============================================================================
__global__ __launch_bounds__(256) void k5_scanA(const float* __restrict__ A_log)
{
    int warp = (blockIdx.x * 256 + threadIdx.x) >> 5;
    int lane = threadIdx.x & 31;
    int dpair = warp & 63;
    int chunk = (warp >> 6) & 63;
    int b = warp >> 12;
    int d = dpair*2 + (lane >> 4);
    int s = lane & 15;
    float A = -__expf(A_log[d*16 + s]);
    float h = 0.f, sdt = 0.f;
    int mbase = b*LL + chunk*CSIZE;
    const float* dtp = g_dt + mbase*128 + d;
    const float* xcp = g_xc + mbase*128 + d;
    const float* bp  = g_Bm + mbase*16 + s;
    #pragma unroll 4
    for (int t = 0; t < CSIZE; t++) {
        float dtv = dtp[t*128];
        float xcv = xcp[t*128];
        float bv  = bp[t*16];
        float dA = __expf(dtv * A);
        h = h*dA + dtv*bv*xcv;
        sdt += dtv;
    }
    int ci = (b*NCHUNK + chunk)*128 + d;
    g_hend[ci*16 + s] = h;
    if (s == 0) g_sumdt[ci] = sdt;
}

// ============================================================================
// K6 (phase B): scan chunk carries: prodA(chunk) = exp(A * sumdt(chunk))
// one thread per (b,d,s) channel
// ============================================================================
__global__ __launch_bounds__(256) void k6_carry(const float* __restrict__ A_log)
{
    int i = blockIdx.x*256 + threadIdx.x;     // 8192 channels
    int s = i & 15;
    int d = (i >> 4) & 127;
    int b = i >> 11;
    float A = -__expf(A_log[d*16+s]);
    float hi = 0.f;
    for (int k = 0; k < NCHUNK; k++) {
        int ci = (b*NCHUNK + k)*128 + d;
        g_hinit[ci*16 + s] = hi;
        hi = hi*__expf(A * g_sumdt[ci]) + g_hend[ci*16 + s];
    }
}

// ============================================================================
// K7 (phase C): replay each chunk from h_init, emit ys (transposed [b,d,l])
// ys = (h.C + xc*Dp) * silu(z)
// ============================================================================
__global__ __launch_bounds__(256) void k7_scanC(
    const float* __restrict__ A_log, const float* __restrict__ Dp)
{
    int warp = (blockIdx.x * 256 + threadIdx.x) >> 5;
    int lane = threadIdx.x & 31;
    int dpair = warp & 63;
    int chunk = (warp >> 6) & 63;
    int b = warp >> 12;
    int d = dpair*2 + (lane >> 4);
    int s = lane & 15;
    float A = -__expf(A_log[d*16+s]);
    int ci = (b*NCHUNK + chunk)*128 + d;
    float h = g_hinit[ci*16 + s];
    float Dv = Dp[d];
    int mbase = b*LL + chunk*CSIZE;
    const float* dtp = g_dt + mbase*128 + d;
    const float* xcp = g_xc + mbase*128 + d;
    const float* zp  = g_z  + mbase*128 + d;
    const float* bp  = g_Bm + mbase*16 + s;
    const float* cp  = g_Cm + mbase*16 + s;
    float* ysp = g_ysT + (b*128 + d)*LL + chunk*CSIZE;
    #pragma unroll 2
    for (int t = 0; t < CSIZE; t++) {
        float dtv = dtp[t*128];
        float xcv = xcp[t*128];
        float bv = bp[t*16];
        float cv = cp[t*16];
        float dA = __expf(dtv*A);
        h = h*dA + dtv*bv*xcv;
        float p = h * cv;
        p += __shfl_xor_sync(0xffffffffu, p, 8, 16);
        p += __shfl_xor_sync(0xffffffffu, p, 4, 16);
        p += __shfl_xor_sync(0xffffffffu, p, 2, 16);
        p += __shfl_xor_sync(0xffffffffu, p, 1, 16);
        if (s == 0) {
            float zv = zp[t*128];
            float sg = 1.f/(1.f + __expf(-zv));
            ysp[t] = (p + xcv*Dv) * (zv*sg);
        }
    }
}

// ============================================================================
// K8: out_proj GEMM (K=128, split in two 64-k blocks) + residual + NCHW write
// block = 64 tokens x 64 channels
// ============================================================================
__global__ __launch_bounds__(256) void k8_outproj(
    const float* __restrict__ Wo, float* __restrict__ out)
{
    __shared__ float sy[64][65];   // ys tile [token][k]
    __shared__ float sw[64][65];   // weight tile [c][k]
    int m0 = blockIdx.x * 64;
    int b = m0 >> 12;
    int l0 = m0 & (LL-1);
    int tid = threadIdx.x;
    int tkn = tid & 63;    // token (lane-consecutive -> coalesced writes on l)
    int cb  = tid >> 6;    // channel base

    float acc[16];
    #pragma unroll
    for (int j = 0; j < 16; j++) acc[j] = 0.f;

    for (int kb = 0; kb < 2; kb++) {
        for (int i = tid; i < 4096; i += 256) {
            int kk = i >> 6, r = i & 63;     // r fastest -> coalesced ysT load
            sy[r][kk] = g_ysT[(b*128 + kb*64 + kk)*LL + l0 + r];
        }
        for (int i = tid; i < 4096; i += 256) {
            int r = i >> 6, kk = i & 63;
            sw[r][kk] = Wo[r*128 + kb*64 + kk];
        }
        __syncthreads();
        #pragma unroll 8
        for (int k = 0; k < 64; k++) {
            float yv = sy[tkn][k];
            #pragma unroll
            for (int j = 0; j < 16; j++) acc[j] += yv * sw[cb + j*4][k];
        }
        __syncthreads();
    }

    int l = l0 + tkn;
    #pragma unroll
    for (int j = 0; j < 16; j++) {
        int cc = cb + j*4;
        int idx = (b*64 + cc)*LL + l;
        out[idx] = acc[j] + g_seqT[idx];
    }
}

// ============================================================================
extern "C" void kernel_launch(void* const* d_in, const int* in_sizes, int n_in,
                              void* d_out, int out_size)
{
    const float* x        = (const float*)d_in[0];
    const float* dwh_w    = (const float*)d_in[1];
    const float* dwh_b    = (const float*)d_in[2];
    const float* dww_w    = (const float*)d_in[3];
    const float* dww_b    = (const float*)d_in[4];
    const float* conv_w   = (const float*)d_in[5];
    const float* conv_b   = (const float*)d_in[6];
    const float* bn_g     = (const float*)d_in[7];
    const float* bn_b     = (const float*)d_in[8];
    const float* bn_m     = (const float*)d_in[9];
    const float* bn_v     = (const float*)d_in[10];
    const float* ln_g     = (const float*)d_in[11];
    const float* ln_b     = (const float*)d_in[12];
    const float* in_proj_w= (const float*)d_in[13];
    const float* convd_w  = (const float*)d_in[14];
    const float* convd_b  = (const float*)d_in[15];
    const float* x_proj_w = (const float*)d_in[16];
    const float* dt_proj_w= (const float*)d_in[17];
    const float* dt_proj_b= (const float*)d_in[18];
    const float* A_log    = (const float*)d_in[19];
    const float* Dp       = (const float*)d_in[20];
    const float* out_proj_w=(const float*)d_in[21];
    float* out = (float*)d_out;

    k1_front<<<BB*64, 256>>>(x, dwh_w, dwh_b, dww_w, dww_b, conv_w, conv_b,
                             bn_g, bn_b, bn_m, bn_v, ln_g, ln_b);
    k2_inproj<<<dim3(NTOK/64, 4), 256>>>(in_proj_w);
    k3_conv1d<<<(NTOK*DI)/256, 256>>>(convd_w, convd_b);
    k4_xproj<<<NTOK/32, 256>>>(x_proj_w, dt_proj_w, dt_proj_b);
    k5_scanA<<<(BB*NCHUNK*(DI/2))/8, 256>>>(A_log);
    k6_carry<<<(BB*DI*DS)/256, 256>>>(A_log);
    k7_scanC<<<(BB*NCHUNK*(DI/2))/8, 256>>>(A_log, Dp);
    k8_outproj<<<NTOK/64, 256>>>(out_proj_w, out);
}

// round 3
// speedup vs baseline: 1.3976x; 1.3976x over previous
#include <cuda_runtime.h>
#include <cuda_bf16.h>

// Problem constants
#define CC      64      // channels
#define DI      128     // d_inner
#define DS      16      // d_state
#define LL      4096    // sequence length H*W
#define BB      4       // batch
#define NTOK    (BB*LL) // 16384 tokens
#define NCHUNK  64
#define CSIZE   64      // LL / NCHUNK

// ---------------- scratch (device globals; no allocation allowed) ------------
__device__ float g_hn   [NTOK*CC];        // LayerNorm output [m, c]
__device__ float g_seqT [BB*CC*LL];       // pre-LN activations, transposed [b,c,l]
__device__ float g_xm   [NTOK*DI];        // in_proj first half [m, d]
__device__ float g_z    [NTOK*DI];        // in_proj second half [m, d]
__device__ float g_xc   [NTOK*DI];        // conv1d+silu output [m, d]
__device__ float g_dt   [NTOK*DI];        // softplus(dt) [m, d]
__device__ float g_Bm   [NTOK*DS];        // [m, s]
__device__ float g_Cm   [NTOK*DS];        // [m, s]
__device__ float g_ysT  [BB*DI*LL];       // scan output, transposed [b,d,l]
__device__ float g_hend [BB*NCHUNK*DI*DS];
__device__ float g_hinit[BB*NCHUNK*DI*DS];
__device__ float g_sumdt[BB*NCHUNK*DI];

// ============================================================================
// K1: axial depthwise convs + 1x1 conv + BN + ReLU + LayerNorm
// one block per (b, h) image row; 64 tokens x 64 channels in smem
// ============================================================================
__global__ __launch_bounds__(256) void k1_front(
    const float* __restrict__ x,
    const float* __restrict__ dwh_w, const float* __restrict__ dwh_b,
    const float* __restrict__ dww_w, const float* __restrict__ dww_b,
    const float* __restrict__ conv_w, const float* __restrict__ conv_b,
    const float* __restrict__ bn_g, const float* __restrict__ bn_b,
    const float* __restrict__ bn_m, const float* __restrict__ bn_v,
    const float* __restrict__ ln_g, const float* __restrict__ ln_b)
{
    __shared__ float sm[64][65];       // m[c][w], later t[c][w]
    __shared__ float scw[64*64];       // 1x1 conv weights
    __shared__ float red_s[64][4];
    __shared__ float red_q[64][4];
    __shared__ float s_mu[64], s_rs[64];

    int bh = blockIdx.x;               // 0..255
    int b = bh >> 6, h = bh & 63;
    int tid = threadIdx.x;

    for (int i = tid; i < 4096; i += 256) scw[i] = conv_w[i];

    // m = x + axial dw convs + biases
    for (int i = tid; i < 4096; i += 256) {
        int c = i >> 6, w = i & 63;
        const float* xb = x + ((b*64 + c)*64)*64;   // + h*64 + w
        float center = xb[h*64 + w];
        float acc = center;
        float wh0 = dwh_w[c*3+0], wh1 = dwh_w[c*3+1], wh2 = dwh_w[c*3+2];
        if (h > 0)  acc += wh0 * xb[(h-1)*64 + w];
        acc += wh1 * center;
        if (h < 63) acc += wh2 * xb[(h+1)*64 + w];
        float ww0 = dww_w[c*3+0], ww1 = dww_w[c*3+1], ww2 = dww_w[c*3+2];
        if (w > 0)  acc += ww0 * xb[h*64 + w - 1];
        acc += ww1 * center;
        if (w < 63) acc += ww2 * xb[h*64 + w + 1];
        acc += dwh_b[c] + dww_b[c];
        sm[c][w] = acc;
    }
    __syncthreads();

    // 1x1 conv + BN + ReLU into registers
    float t[16];
    #pragma unroll
    for (int j = 0; j < 16; j++) {
        int i = tid + j*256;
        int o = i >> 6, w = i & 63;
        float acc = 0.f;
        #pragma unroll 8
        for (int c = 0; c < 64; c++) acc += scw[o*64+c]*sm[c][w];
        acc += conv_b[o];
        float rs = rsqrtf(bn_v[o] + 1e-5f);
        acc = (acc - bn_m[o]) * rs * bn_g[o] + bn_b[o];
        t[j] = fmaxf(acc, 0.f);
    }
    __syncthreads();
    #pragma unroll
    for (int j = 0; j < 16; j++) {
        int i = tid + j*256;
        sm[i>>6][i&63] = t[j];
    }
    __syncthreads();

    // LayerNorm over channels per token
    {
        int w = tid & 63, p = tid >> 6;
        float s = 0.f, q = 0.f;
        #pragma unroll
        for (int c = p*16; c < p*16+16; c++) { float v = sm[c][w]; s += v; q += v*v; }
        red_s[w][p] = s; red_q[w][p] = q;
    }
    __syncthreads();
    if (tid < 64) {
        float s = red_s[tid][0]+red_s[tid][1]+red_s[tid][2]+red_s[tid][3];
        float q = red_q[tid][0]+red_q[tid][1]+red_q[tid][2]+red_q[tid][3];
        float mu = s * (1.f/64.f);
        float var = q * (1.f/64.f) - mu*mu;
        s_mu[tid] = mu;
        s_rs[tid] = rsqrtf(var + 1e-5f);
    }
    __syncthreads();

    int mbase = b*LL + h*64;   // token base for this row
    // hn writes: c fastest -> coalesced
    for (int i = tid; i < 4096; i += 256) {
        int w = i >> 6, c = i & 63;
        float v = sm[c][w];
        g_hn[(mbase + w)*64 + c] = (v - s_mu[w]) * s_rs[w] * ln_g[c] + ln_b[c];
    }
    // seqT writes [b,c,l]: w fastest -> coalesced
    for (int i = tid; i < 4096; i += 256) {
        int c = i >> 6, w = i & 63;
        g_seqT[(b*64 + c)*LL + h*64 + w] = sm[c][w];
    }
}

// ============================================================================
// K2: in_proj GEMM  xz[m, 0..255] = hn[m, :] @ W^T ; split into xm / z
// block tile: 64 tokens x 64 outputs; 4x4 register blocking per thread
// ============================================================================
__global__ __launch_bounds__(256) void k2_inproj(const float* __restrict__ W)
{
    __shared__ float sa[64][65];   // hn tile [token][k]
    __shared__ float sw[64][65];   // weight tile [o][k]
    int m0 = blockIdx.x * 64;
    int n0 = blockIdx.y * 64;
    int tid = threadIdx.x;
    for (int i = tid; i < 4096; i += 256) {
        int r = i >> 6, kk = i & 63;
        sa[r][kk] = g_hn[(m0+r)*64 + kk];
        sw[r][kk] = W[(n0+r)*64 + kk];
    }
    __syncthreads();

    int o0 = tid & 15;     // outputs o0 + 16*b  (lane-consecutive)
    int t0 = tid >> 4;     // tokens  t0 + 16*a
    float acc[4][4];
    #pragma unroll
    for (int a = 0; a < 4; a++)
        #pragma unroll
        for (int bb = 0; bb < 4; bb++) acc[a][bb] = 0.f;

    #pragma unroll 4
    for (int k = 0; k < 64; k++) {
        float av[4], wv[4];
        #pragma unroll
        for (int a = 0; a < 4; a++)  av[a] = sa[t0 + 16*a][k];
        #pragma unroll
        for (int bb = 0; bb < 4; bb++) wv[bb] = sw[o0 + 16*bb][k];
        #pragma unroll
        for (int a = 0; a < 4; a++)
            #pragma unroll
            for (int bb = 0; bb < 4; bb++) acc[a][bb] += av[a]*wv[bb];
    }

    #pragma unroll
    for (int a = 0; a < 4; a++) {
        int m = m0 + t0 + 16*a;
        #pragma unroll
        for (int bb = 0; bb < 4; bb++) {
            int og = n0 + o0 + 16*bb;
            if (og < 128) g_xm[m*128 + og]       = acc[a][bb];
            else          g_z [m*128 + og - 128] = acc[a][bb];
        }
    }
}

// ============================================================================
// K3: causal depthwise conv1d (k=4, left pad 3) + SiLU
// ============================================================================
__global__ __launch_bounds__(256) void k3_conv1d(
    const float* __restrict__ cw, const float* __restrict__ cb)
{
    int i = blockIdx.x*256 + threadIdx.x;      // over NTOK*DI
    int d = i & 127;
    int m = i >> 7;
    int l = m & (LL-1);
    float acc = cb[d];
    acc += cw[d*4+3] * g_xm[i];
    if (l >= 1) acc += cw[d*4+2] * g_xm[i - 128];
    if (l >= 2) acc += cw[d*4+1] * g_xm[i - 256];
    if (l >= 3) acc += cw[d*4+0] * g_xm[i - 384];
    float sg = 1.f/(1.f + __expf(-acc));
    g_xc[i] = acc * sg;
}

// ============================================================================
// K4: x_proj (36x128) + dt_proj (128x4) + softplus; writes dt, Bm, Cm
// block = 64 tokens. Weights stored TRANSPOSED in smem (conflict-free),
// 8-token register blocking for the 32 B/C outputs.
// ============================================================================
__global__ __launch_bounds__(256) void k4_xproj(
    const float* __restrict__ xpw,   // [36][128]
    const float* __restrict__ dtw,   // [128][4]
    const float* __restrict__ dtb)   // [128]
{
    __shared__ float swt[128][33];   // swt[k][o] = xpw[4+o][k]   (B/C rows)
    __shared__ float swr[128][5];    // swr[k][r] = xpw[r][k]     (dt-rank rows)
    __shared__ float sxc[64][65];    // xc tile for one 64-k half
    __shared__ float sdtr[64][5];    // rank dots per token

    int m0 = blockIdx.x * 64;
    int tid = threadIdx.x;

    for (int i = tid; i < 32*128; i += 256) {
        int o = i >> 7, k = i & 127;
        swt[k][o] = xpw[(4+o)*128 + k];
    }
    for (int i = tid; i < 4*128; i += 256) {
        int r = i >> 7, k = i & 127;
        swr[k][r] = xpw[r*128 + k];
    }

    int o  = tid & 31;     // B/C output index (0..31)
    int tb = tid >> 5;     // token group (0..7), 8 tokens each
    int t4 = tid >> 2;     // rank-dot token (0..63)
    int r  = tid & 3;      // rank index

    float acc[8];
    #pragma unroll
    for (int j = 0; j < 8; j++) acc[j] = 0.f;
    float accr = 0.f;

    for (int kb = 0; kb < 2; kb++) {
        __syncthreads();
        for (int i = tid; i < 4096; i += 256) {
            int t = i >> 6, kk = i & 63;
            sxc[t][kk] = g_xc[(m0 + t)*128 + kb*64 + kk];
        }
        __syncthreads();
        #pragma unroll 4
        for (int k = 0; k < 64; k++) {
            float wv = swt[kb*64 + k][o];
            #pragma unroll
            for (int j = 0; j < 8; j++) acc[j] += sxc[tb*8 + j][k] * wv;
        }
        #pragma unroll 4
        for (int k = 0; k < 64; k++)
            accr += sxc[t4][k] * swr[kb*64 + k][r];
    }

    // write B/C
    #pragma unroll
    for (int j = 0; j < 8; j++) {
        int m = m0 + tb*8 + j;
        if (o < 16) g_Bm[m*16 + o]      = acc[j];
        else        g_Cm[m*16 + o - 16] = acc[j];
    }

    sdtr[t4][r] = accr;
    __syncthreads();

    // dt_proj + softplus
    for (int i = tid; i < 64*128; i += 256) {
        int t = i >> 7, d = i & 127;
        float a = dtb[d];
        #pragma unroll
        for (int rr = 0; rr < 4; rr++) a += sdtr[t][rr] * dtw[d*4 + rr];
        g_dt[(m0+t)*128 + d] = (a > 20.f) ? a : log1pf(__expf(a));
    }
}

// ============================================================================
// K5 (phase A): per-chunk local scan starting at 0 -> h_end, sum(dt)
// warp handles (b, chunk, 2 d's); lane = s + 16*(d&1)
// ============================================================================
__global__ __launch_bounds__(256) void k5_scanA(const float* __restrict__ A_log)
{
    int warp = (blockIdx.x * 256 + threadIdx.x) >> 5;
    int lane = threadIdx.x & 31;
    int dpair = warp & 63;
    int chunk = (warp >> 6) & 63;
    int b = warp >> 12;
    int d = dpair*2 + (lane >> 4);
    int s = lane & 15;
    float A = -__expf(A_log[d*16 + s]);
    float h = 0.f, sdt = 0.f;
    int mbase = b*LL + chunk*CSIZE;
    const float* dtp = g_dt + mbase*128 + d;
    const float* xcp = g_xc + mbase*128 + d;
    const float* bp  = g_Bm + mbase*16 + s;
    #pragma unroll 4
    for (int t = 0; t < CSIZE; t++) {
        float dtv = dtp[t*128];
        float xcv = xcp[t*128];
        float bv  = bp[t*16];
        float dA = __expf(dtv * A);
        h = h*dA + dtv*bv*xcv;
        sdt += dtv;
    }
    int ci = (b*NCHUNK + chunk)*128 + d;
    g_hend[ci*16 + s] = h;
    if (s == 0) g_sumdt[ci] = sdt;
}

// ============================================================================
// K6 (phase B): scan chunk carries: prodA(chunk) = exp(A * sumdt(chunk))
// one thread per (b,d,s) channel
// ============================================================================
__global__ __launch_bounds__(256) void k6_carry(const float* __restrict__ A_log)
{
    int i = blockIdx.x*256 + threadIdx.x;     // 8192 channels
    int s = i & 15;
    int d = (i >> 4) & 127;
    int b = i >> 11;
    float A = -__expf(A_log[d*16+s]);
    float hi = 0.f;
    #pragma unroll 4
    for (int k = 0; k < NCHUNK; k++) {
        int ci = (b*NCHUNK + k)*128 + d;
        g_hinit[ci*16 + s] = hi;
        hi = hi*__expf(A * g_sumdt[ci]) + g_hend[ci*16 + s];
    }
}

// ============================================================================
// K7 (phase C): replay each chunk from h_init, emit ys (transposed [b,d,l])
// ys = (h.C + xc*Dp) * silu(z)
// ============================================================================
__global__ __launch_bounds__(256) void k7_scanC(
    const float* __restrict__ A_log, const float* __restrict__ Dp)
{
    int warp = (blockIdx.x * 256 + threadIdx.x) >> 5;
    int lane = threadIdx.x & 31;
    int dpair = warp & 63;
    int chunk = (warp >> 6) & 63;
    int b = warp >> 12;
    int d = dpair*2 + (lane >> 4);
    int s = lane & 15;
    float A = -__expf(A_log[d*16+s]);
    int ci = (b*NCHUNK + chunk)*128 + d;
    float h = g_hinit[ci*16 + s];
    float Dv = Dp[d];
    int mbase = b*LL + chunk*CSIZE;
    const float* dtp = g_dt + mbase*128 + d;
    const float* xcp = g_xc + mbase*128 + d;
    const float* zp  = g_z  + mbase*128 + d;
    const float* bp  = g_Bm + mbase*16 + s;
    const float* cp  = g_Cm + mbase*16 + s;
    float* ysp = g_ysT + (b*128 + d)*LL + chunk*CSIZE;
    #pragma unroll 2
    for (int t = 0; t < CSIZE; t++) {
        float dtv = dtp[t*128];
        float xcv = xcp[t*128];
        float bv = bp[t*16];
        float cv = cp[t*16];
        float dA = __expf(dtv*A);
        h = h*dA + dtv*bv*xcv;
        float p = h * cv;
        p += __shfl_xor_sync(0xffffffffu, p, 8, 16);
        p += __shfl_xor_sync(0xffffffffu, p, 4, 16);
        p += __shfl_xor_sync(0xffffffffu, p, 2, 16);
        p += __shfl_xor_sync(0xffffffffu, p, 1, 16);
        if (s == 0) {
            float zv = zp[t*128];
            float sg = 1.f/(1.f + __expf(-zv));
            ysp[t] = (p + xcv*Dv) * (zv*sg);
        }
    }
}

// ============================================================================
// K8: out_proj GEMM (K=128, split in two 64-k blocks) + residual + NCHW write
// block = 64 tokens x 64 channels; 4x4 register blocking per thread
// ============================================================================
__global__ __launch_bounds__(256) void k8_outproj(
    const float* __restrict__ Wo, float* __restrict__ out)
{
    __shared__ float sy[64][65];   // ys tile [token][k]
    __shared__ float sw[64][65];   // weight tile [c][k]
    int m0 = blockIdx.x * 64;
    int b = m0 >> 12;
    int l0 = m0 & (LL-1);
    int tid = threadIdx.x;
    int t0 = tid & 15;    // token (lane-consecutive) + 16*a
    int c0 = tid >> 4;    // channel + 16*bb

    float acc[4][4];
    #pragma unroll
    for (int a = 0; a < 4; a++)
        #pragma unroll
        for (int bb = 0; bb < 4; bb++) acc[a][bb] = 0.f;

    for (int kb = 0; kb < 2; kb++) {
        if (kb) __syncthreads();
        for (int i = tid; i < 4096; i += 256) {
            int kk = i >> 6, r = i & 63;     // r fastest -> coalesced ysT load
            sy[r][kk] = g_ysT[(b*128 + kb*64 + kk)*LL + l0 + r];
        }
        for (int i = tid; i < 4096; i += 256) {
            int r = i >> 6, kk = i & 63;
            sw[r][kk] = Wo[r*128 + kb*64 + kk];
        }
        __syncthreads();
        #pragma unroll 4
        for (int k = 0; k < 64; k++) {
            float av[4], wv[4];
            #pragma unroll
            for (int a = 0; a < 4; a++)  av[a] = sy[t0 + 16*a][k];
            #pragma unroll
            for (int bb = 0; bb < 4; bb++) wv[bb] = sw[c0 + 16*bb][k];
            #pragma unroll
            for (int a = 0; a < 4; a++)
                #pragma unroll
                for (int bb = 0; bb < 4; bb++) acc[a][bb] += av[a]*wv[bb];
        }
    }

    #pragma unroll
    for (int a = 0; a < 4; a++) {
        int l = l0 + t0 + 16*a;
        #pragma unroll
        for (int bb = 0; bb < 4; bb++) {
            int cc = c0 + 16*bb;
            int idx = (b*64 + cc)*LL + l;
            out[idx] = acc[a][bb] + g_seqT[idx];
        }
    }
}

// ============================================================================
extern "C" void kernel_launch(void* const* d_in, const int* in_sizes, int n_in,
                              void* d_out, int out_size)
{
    const float* x        = (const float*)d_in[0];
    const float* dwh_w    = (const float*)d_in[1];
    const float* dwh_b    = (const float*)d_in[2];
    const float* dww_w    = (const float*)d_in[3];
    const float* dww_b    = (const float*)d_in[4];
    const float* conv_w   = (const float*)d_in[5];
    const float* conv_b   = (const float*)d_in[6];
    const float* bn_g     = (const float*)d_in[7];
    const float* bn_b     = (const float*)d_in[8];
    const float* bn_m     = (const float*)d_in[9];
    const float* bn_v     = (const float*)d_in[10];
    const float* ln_g     = (const float*)d_in[11];
    const float* ln_b     = (const float*)d_in[12];
    const float* in_proj_w= (const float*)d_in[13];
    const float* convd_w  = (const float*)d_in[14];
    const float* convd_b  = (const float*)d_in[15];
    const float* x_proj_w = (const float*)d_in[16];
    const float* dt_proj_w= (const float*)d_in[17];
    const float* dt_proj_b= (const float*)d_in[18];
    const float* A_log    = (const float*)d_in[19];
    const float* Dp       = (const float*)d_in[20];
    const float* out_proj_w=(const float*)d_in[21];
    float* out = (float*)d_out;

    k1_front<<<BB*64, 256>>>(x, dwh_w, dwh_b, dww_w, dww_b, conv_w, conv_b,
                             bn_g, bn_b, bn_m, bn_v, ln_g, ln_b);
    k2_inproj<<<dim3(NTOK/64, 4), 256>>>(in_proj_w);
    k3_conv1d<<<(NTOK*DI)/256, 256>>>(convd_w, convd_b);
    k4_xproj<<<NTOK/64, 256>>>(x_proj_w, dt_proj_w, dt_proj_b);
    k5_scanA<<<(BB*NCHUNK*(DI/2))/8, 256>>>(A_log);
    k6_carry<<<(BB*DI*DS)/256, 256>>>(A_log);
    k7_scanC<<<(BB*NCHUNK*(DI/2))/8, 256>>>(A_log, Dp);
    k8_outproj<<<NTOK/64, 256>>>(out_proj_w, out);
}